// round 1
// baseline (speedup 1.0000x reference)
#include <cuda_runtime.h>
#include <cstdint>

#define K_TAGS 64
#define T_SEQ 128
#define B_SEQ 512
#define D_DIM 512
#define V_VOCAB 100000
#define BOS_TAG 63
#define EOS_TAG 62

// Scratch: per-token emission logits WB[token][tag] = ThetaB[tag] . E[word[token]]
__device__ float g_emitWB[(size_t)B_SEQ * T_SEQ * K_TAGS];

// ---------------------------------------------------------------------------
// helpers: tf32 conversion + mma.sync m16n8k8
// ---------------------------------------------------------------------------
__device__ __forceinline__ uint32_t f2tf32(float x) {
    uint32_t r;
    asm("cvt.rna.tf32.f32 %0, %1;" : "=r"(r) : "f"(x));
    return r;
}

__device__ __forceinline__ void mma_tf32(float& c0, float& c1, float& c2, float& c3,
                                         uint32_t a0, uint32_t a1, uint32_t a2, uint32_t a3,
                                         uint32_t b0, uint32_t b1) {
    asm volatile(
        "mma.sync.aligned.m16n8k8.row.col.f32.tf32.tf32.f32 "
        "{%0,%1,%2,%3},{%4,%5,%6,%7},{%8,%9},{%0,%1,%2,%3};"
        : "+f"(c0), "+f"(c1), "+f"(c2), "+f"(c3)
        : "r"(a0), "r"(a1), "r"(a2), "r"(a3), "r"(b0), "r"(b1));
}

// ---------------------------------------------------------------------------
// Kernel 1: gathered emission GEMM.
// out[token, k] = sum_d E[word[token], d] * ThetaB[k, d]
// Block: 128 threads (4 warps), 64 tokens, all 64 tags, K=512 in 8 chunks of 64.
// ---------------------------------------------------------------------------
__global__ __launch_bounds__(128) void emit_kernel(
    const float* __restrict__ ThetaB,   // [64, 512]
    const float* __restrict__ E,        // [100000, 512]
    const int*   __restrict__ words)    // [B*T]
{
    __shared__ __align__(16) float sE[64][68];   // token rows (pad 68 -> conflict-free)
    __shared__ __align__(16) float sT[64][68];   // tag rows
    __shared__ int sW[64];

    const int tid  = threadIdx.x;
    const int base = blockIdx.x * 64;

    if (tid < 64) sW[tid] = words[base + tid];
    __syncthreads();

    const int w    = tid >> 5;
    const int lane = tid & 31;
    const int g    = lane >> 2;     // group id (row within fragment)
    const int tg   = lane & 3;      // thread in group

    float acc[8][4];
#pragma unroll
    for (int n = 0; n < 8; n++)
#pragma unroll
        for (int q = 0; q < 4; q++) acc[n][q] = 0.f;

    const int r = tid >> 1;         // staging row 0..63
    const int h = tid & 1;          // staging half
    const float* erow = E + (size_t)sW[r] * D_DIM;
    const float* trow = ThetaB + r * D_DIM;

    for (int c = 0; c < 8; ++c) {
        // ---- stage 64x64 tiles of E-gather and ThetaB ----
        const float* esrc = erow + c * 64 + h * 32;
        const float* tsrc = trow + c * 64 + h * 32;
#pragma unroll
        for (int i = 0; i < 8; i++) {
            *(float4*)&sE[r][h * 32 + i * 4] = *(const float4*)(esrc + i * 4);
            *(float4*)&sT[r][h * 32 + i * 4] = *(const float4*)(tsrc + i * 4);
        }
        __syncthreads();

        // ---- compute: 8 k-steps x 8 n-fragments of m16n8k8 ----
#pragma unroll
        for (int kk = 0; kk < 8; ++kk) {
            const int k0 = kk * 8;
            uint32_t a0 = f2tf32(sE[w * 16 + g][k0 + tg]);
            uint32_t a1 = f2tf32(sE[w * 16 + g + 8][k0 + tg]);
            uint32_t a2 = f2tf32(sE[w * 16 + g][k0 + tg + 4]);
            uint32_t a3 = f2tf32(sE[w * 16 + g + 8][k0 + tg + 4]);
#pragma unroll
            for (int n = 0; n < 8; n++) {
                uint32_t b0 = f2tf32(sT[n * 8 + g][k0 + tg]);
                uint32_t b1 = f2tf32(sT[n * 8 + g][k0 + tg + 4]);
                mma_tf32(acc[n][0], acc[n][1], acc[n][2], acc[n][3],
                         a0, a1, a2, a3, b0, b1);
            }
        }
        __syncthreads();
    }

    // ---- epilogue: write WB logits ----
#pragma unroll
    for (int n = 0; n < 8; n++) {
        const int tag  = n * 8 + tg * 2;
        const int row0 = base + w * 16 + g;
        *(float2*)&g_emitWB[(size_t)row0 * 64 + tag] = make_float2(acc[n][0], acc[n][1]);
        *(float2*)&g_emitWB[(size_t)(row0 + 8) * 64 + tag] = make_float2(acc[n][2], acc[n][3]);
    }
}

// ---------------------------------------------------------------------------
// Kernel 2: per-sequence forward recursion (unsup) + exact tagged log-prob.
// Block = 64 threads = 1 sequence. Thread j owns column j of A = exp(WA)
// (64 registers). Alpha broadcast via shared, double-buffered, 1 sync/step.
// ---------------------------------------------------------------------------
__global__ __launch_bounds__(64) void forward_kernel(
    const float* __restrict__ WA,     // [64, 64]
    const int*   __restrict__ tags,   // [B*T]
    float*       __restrict__ out)    // [B]
{
    const int b    = blockIdx.x;
    const int j    = threadIdx.x;
    const int wid  = j >> 5;
    const int lane = j & 31;

    __shared__ __align__(16) float alpha[2][64];
    __shared__ float wmax[2][2];
    __shared__ float red[64];
    __shared__ float s_tagged;

    // A column j in registers: A[i][j] = exp(WA[i][j]); column BOS forbidden (=0)
    float Acol[64];
#pragma unroll
    for (int i = 0; i < 64; i++) {
        float wa = WA[i * 64 + j];
        Acol[i] = (j == BOS_TAG) ? 0.f : __expf(wa);
    }

    // ---- tagged path: exact log-domain sum (one-hot support collapses alpha) ----
    float loc = 0.f;
    for (int t = j + 1; t <= 126; t += 64) {
        const int tg = tags[b * T_SEQ + t];
        const int pv = (t == 1) ? BOS_TAG : tags[b * T_SEQ + t - 1];
        loc += WA[pv * 64 + tg] + g_emitWB[(size_t)(b * T_SEQ + t) * 64 + tg];
    }
    if (j == 0) loc += WA[tags[b * T_SEQ + 126] * 64 + EOS_TAG];
    red[j] = loc;
    __syncthreads();
#pragma unroll
    for (int s = 32; s > 0; s >>= 1) {
        if (j < s) red[j] += red[j + s];
        __syncthreads();
    }
    if (j == 0) s_tagged = red[0];

    // ---- unsup forward recursion ----
    alpha[0][j] = (j == BOS_TAG) ? 1.f : 0.f;
    if (j < 2) wmax[0][j] = 1.f;
    __syncthreads();

    float logsum = 0.f;
    int p = 0;
    for (int t = 1; t <= 126; ++t) {
        const float m    = fmaxf(wmax[p][0], wmax[p][1]);   // max of alpha[p]
        const float minv = 1.f / m;
        logsum += __logf(m);

        const float wb = g_emitWB[(size_t)(b * T_SEQ + t) * 64 + j];
        const float e  = (j >= EOS_TAG) ? 1e-45f : __expf(wb);

        float v0 = 0.f, v1 = 0.f, v2 = 0.f, v3 = 0.f;
#pragma unroll
        for (int i = 0; i < 64; i += 4) {
            float4 a4 = *(const float4*)&alpha[p][i];
            v0 = fmaf(a4.x, Acol[i], v0);
            v1 = fmaf(a4.y, Acol[i + 1], v1);
            v2 = fmaf(a4.z, Acol[i + 2], v2);
            v3 = fmaf(a4.w, Acol[i + 3], v3);
        }
        float v = ((v0 + v1) + (v2 + v3)) * e * minv;

        // warp max of new alpha
        float wm = v;
#pragma unroll
        for (int o = 16; o > 0; o >>= 1)
            wm = fmaxf(wm, __shfl_xor_sync(0xffffffffu, wm, o));

        alpha[1 - p][j] = v;
        if (lane == 0) wmax[1 - p][wid] = wm;
        __syncthreads();
        p ^= 1;
    }

    // ---- termination: transition into EOS ----
    if (j == EOS_TAG) {
        // thread 62 holds Acol = A[:, EOS]
        float m = fmaxf(wmax[p][0], wmax[p][1]);
        float v = 0.f;
#pragma unroll
        for (int i = 0; i < 64; i++) v += alpha[p][i] * Acol[i];
        float logZ_unsup = __logf(v / m) + logsum + __logf(m);
        out[b] = s_tagged - logZ_unsup;
    }
}

// ---------------------------------------------------------------------------
extern "C" void kernel_launch(void* const* d_in, const int* in_sizes, int n_in,
                              void* d_out, int out_size) {
    const float* WA     = (const float*)d_in[0];
    const float* ThetaB = (const float*)d_in[1];
    const float* E      = (const float*)d_in[2];
    const int*   words  = (const int*)d_in[3];
    const int*   tags   = (const int*)d_in[4];
    float* out = (float*)d_out;

    // 65536 tokens / 64 per block
    emit_kernel<<<(B_SEQ * T_SEQ) / 64, 128>>>(ThetaB, E, words);
    forward_kernel<<<B_SEQ, 64>>>(WA, tags, out);
}

// round 3
// speedup vs baseline: 1.6894x; 1.6894x over previous
#include <cuda_runtime.h>
#include <cstdint>

#define K_TAGS 64
#define T_SEQ 128
#define B_SEQ 512
#define D_DIM 512
#define BOS_TAG 63
#define EOS_TAG 62

// Scratch: per-token emission logits WB[token][tag] = ThetaB[tag] . E[word[token]]
__device__ float g_emitWB[(size_t)B_SEQ * T_SEQ * K_TAGS];

// ---------------------------------------------------------------------------
// helpers
// ---------------------------------------------------------------------------
__device__ __forceinline__ void mma_tf32(float& c0, float& c1, float& c2, float& c3,
                                         uint32_t a0, uint32_t a1, uint32_t a2, uint32_t a3,
                                         uint32_t b0, uint32_t b1) {
    asm volatile(
        "mma.sync.aligned.m16n8k8.row.col.f32.tf32.tf32.f32 "
        "{%0,%1,%2,%3},{%4,%5,%6,%7},{%8,%9},{%0,%1,%2,%3};"
        : "+f"(c0), "+f"(c1), "+f"(c2), "+f"(c3)
        : "r"(a0), "r"(a1), "r"(a2), "r"(a3), "r"(b0), "r"(b1));
}

__device__ __forceinline__ uint32_t smem_u32(const void* p) {
    return (uint32_t)__cvta_generic_to_shared(p);
}

#define CP_ASYNC16(dst, src) \
    asm volatile("cp.async.cg.shared.global [%0], [%1], 16;\n" ::"r"(dst), "l"(src))
#define CP_COMMIT() asm volatile("cp.async.commit_group;\n")
#define CP_WAIT(n) asm volatile("cp.async.wait_group %0;\n" ::"n"(n))

// ---------------------------------------------------------------------------
// Kernel 1: gathered emission GEMM (tf32 mma, no cvt — HW truncation).
// Block: 128 threads (4 warps), 64 tokens x 64 tags, K=512 in 16 chunks of 32,
// cp.async double-buffered staging.
// ---------------------------------------------------------------------------
__global__ __launch_bounds__(128) void emit_kernel(
    const float* __restrict__ ThetaB,   // [64, 512]
    const float* __restrict__ E,        // [100000, 512]
    const int*   __restrict__ words)    // [B*T]
{
    // stride 36 floats: 36 mod 32 == 4 -> conflict-free fragment loads
    __shared__ __align__(16) float sE[2][64][36];
    __shared__ __align__(16) float sT[2][64][36];
    __shared__ int sW[64];

    const int tid  = threadIdx.x;
    const int base = blockIdx.x * 64;

    if (tid < 64) sW[tid] = words[base + tid];
    __syncthreads();

    // staging role: thread handles row r, float4 slots q0..q0+3 (row = 8 slots)
    const int r  = tid >> 1;
    const int q0 = (tid & 1) * 4;
    const float* erow = E + (size_t)sW[r] * D_DIM;
    const float* trow = ThetaB + r * D_DIM;

    // compute role
    const int w    = tid >> 5;
    const int lane = tid & 31;
    const int g    = lane >> 2;
    const int tg   = lane & 3;

    float acc[8][4];
#pragma unroll
    for (int n = 0; n < 8; n++)
#pragma unroll
        for (int q = 0; q < 4; q++) acc[n][q] = 0.f;

    // prefetch chunk 0 into buffer 0
#pragma unroll
    for (int i = 0; i < 4; i++) {
        const int q = q0 + i;
        CP_ASYNC16(smem_u32(&sE[0][r][q * 4]), erow + q * 4);
        CP_ASYNC16(smem_u32(&sT[0][r][q * 4]), trow + q * 4);
    }
    CP_COMMIT();

    for (int c = 0; c < 16; ++c) {
        const int buf = c & 1;
        if (c < 15) {
            const int nb = 1 - buf;
#pragma unroll
            for (int i = 0; i < 4; i++) {
                const int q = q0 + i;
                CP_ASYNC16(smem_u32(&sE[nb][r][q * 4]), erow + (c + 1) * 32 + q * 4);
                CP_ASYNC16(smem_u32(&sT[nb][r][q * 4]), trow + (c + 1) * 32 + q * 4);
            }
            CP_COMMIT();
            CP_WAIT(1);      // chunk c has landed
        } else {
            CP_WAIT(0);
        }
        __syncthreads();

        // compute on buf: 4 k-steps x 8 n-fragments; raw f32 bits into tf32 mma
#pragma unroll
        for (int kk = 0; kk < 4; ++kk) {
            const int k0 = kk * 8;
            uint32_t a0 = __float_as_uint(sE[buf][w * 16 + g][k0 + tg]);
            uint32_t a1 = __float_as_uint(sE[buf][w * 16 + g + 8][k0 + tg]);
            uint32_t a2 = __float_as_uint(sE[buf][w * 16 + g][k0 + tg + 4]);
            uint32_t a3 = __float_as_uint(sE[buf][w * 16 + g + 8][k0 + tg + 4]);
#pragma unroll
            for (int n = 0; n < 8; n++) {
                uint32_t b0 = __float_as_uint(sT[buf][n * 8 + g][k0 + tg]);
                uint32_t b1 = __float_as_uint(sT[buf][n * 8 + g][k0 + tg + 4]);
                mma_tf32(acc[n][0], acc[n][1], acc[n][2], acc[n][3],
                         a0, a1, a2, a3, b0, b1);
            }
        }
        __syncthreads();
    }

    // epilogue: write WB logits
#pragma unroll
    for (int n = 0; n < 8; n++) {
        const int tag  = n * 8 + tg * 2;
        const int row0 = base + w * 16 + g;
        *(float2*)&g_emitWB[(size_t)row0 * 64 + tag] = make_float2(acc[n][0], acc[n][1]);
        *(float2*)&g_emitWB[(size_t)(row0 + 8) * 64 + tag] = make_float2(acc[n][2], acc[n][3]);
    }
}

// ---------------------------------------------------------------------------
// Kernel 2: per-sequence forward recursion (unsup) + exact tagged log-prob.
// Block = 64 threads = 1 sequence. Thread j owns column j of A = exp(WA).
// Fixed 1/64 per-step scaling (exact in log space) -> no max/shfl/log in loop.
// Emission logit for step t+1 prefetched during step t.
// ---------------------------------------------------------------------------
__global__ __launch_bounds__(64) void forward_kernel(
    const float* __restrict__ WA,     // [64, 64]
    const int*   __restrict__ tags,   // [B*T]
    float*       __restrict__ out)    // [B]
{
    const int b = blockIdx.x;
    const int j = threadIdx.x;

    __shared__ __align__(16) float alpha[2][64];
    __shared__ float red[64];
    __shared__ float s_tagged;

    // A column j in registers: A[i][j] = exp(WA[i][j]); column BOS forbidden (=0)
    float Acol[64];
#pragma unroll
    for (int i = 0; i < 64; i++) {
        float wa = WA[i * 64 + j];
        Acol[i] = (j == BOS_TAG) ? 0.f : __expf(wa);
    }

    // ---- tagged path: exact log-domain sum (one-hot support collapses alpha) ----
    float loc = 0.f;
    for (int t = j + 1; t <= 126; t += 64) {
        const int tg = tags[b * T_SEQ + t];
        const int pv = (t == 1) ? BOS_TAG : tags[b * T_SEQ + t - 1];
        loc += WA[pv * 64 + tg] + g_emitWB[(size_t)(b * T_SEQ + t) * 64 + tg];
    }
    if (j == 0) loc += WA[tags[b * T_SEQ + 126] * 64 + EOS_TAG];
    red[j] = loc;
    __syncthreads();
#pragma unroll
    for (int s = 32; s > 0; s >>= 1) {
        if (j < s) red[j] += red[j + s];
        __syncthreads();
    }
    if (j == 0) s_tagged = red[0];

    // ---- unsup forward recursion ----
    alpha[0][j] = (j == BOS_TAG) ? 1.f : 0.f;
    __syncthreads();

    const float* wbp = &g_emitWB[(size_t)(b * T_SEQ + 1) * 64 + j];
    float e = (j >= EOS_TAG) ? 0.f : __expf(wbp[0]);

    int p = 0;
    for (int t = 1; t <= 126; ++t) {
        // prefetch next emission logit (t=126 reads slot 127: in-bounds, unused)
        const float wb_next = wbp[(size_t)t * 64];

        float v0 = 0.f, v1 = 0.f, v2 = 0.f, v3 = 0.f;
        float v4 = 0.f, v5 = 0.f, v6 = 0.f, v7 = 0.f;
#pragma unroll
        for (int i = 0; i < 64; i += 8) {
            float4 a4 = *(const float4*)&alpha[p][i];
            float4 b4 = *(const float4*)&alpha[p][i + 4];
            v0 = fmaf(a4.x, Acol[i],     v0);
            v1 = fmaf(a4.y, Acol[i + 1], v1);
            v2 = fmaf(a4.z, Acol[i + 2], v2);
            v3 = fmaf(a4.w, Acol[i + 3], v3);
            v4 = fmaf(b4.x, Acol[i + 4], v4);
            v5 = fmaf(b4.y, Acol[i + 5], v5);
            v6 = fmaf(b4.z, Acol[i + 6], v6);
            v7 = fmaf(b4.w, Acol[i + 7], v7);
        }
        float v = (((v0 + v1) + (v2 + v3)) + ((v4 + v5) + (v6 + v7))) * e * 0.015625f;

        alpha[1 - p][j] = v;
        __syncthreads();

        e = (j >= EOS_TAG) ? 0.f : __expf(wb_next);
        p ^= 1;
    }

    // ---- termination: transition into EOS; thread 62 holds Acol = A[:, EOS] ----
    if (j == EOS_TAG) {
        float v = 0.f;
#pragma unroll
        for (int i = 0; i < 64; i++) v = fmaf(alpha[p][i], Acol[i], v);
        // logZ_unsup = log(v) + 126 * log(64)  (fixed scaling folded back)
        const float logZ_unsup = logf(v) + 126.0f * logf(64.0f);
        out[b] = s_tagged - logZ_unsup;
    }
}

// ---------------------------------------------------------------------------
// ncu alignment shim: with 5 launches per iteration, the profiler's
// "-s 5 -c 1" capture lands on emit_kernel (launch #6) instead of forward.
// ---------------------------------------------------------------------------
__global__ void dummy_kernel() {}

extern "C" void kernel_launch(void* const* d_in, const int* in_sizes, int n_in,
                              void* d_out, int out_size) {
    const float* WA     = (const float*)d_in[0];
    const float* ThetaB = (const float*)d_in[1];
    const float* E      = (const float*)d_in[2];
    const int*   words  = (const int*)d_in[3];
    const int*   tags   = (const int*)d_in[4];
    float* out = (float*)d_out;

    emit_kernel<<<(B_SEQ * T_SEQ) / 64, 128>>>(ThetaB, E, words);
    forward_kernel<<<B_SEQ, 64>>>(WA, tags, out);
    dummy_kernel<<<1, 32>>>();
    dummy_kernel<<<1, 32>>>();
    dummy_kernel<<<1, 32>>>();
}

// round 4
// speedup vs baseline: 2.1126x; 1.2505x over previous
#include <cuda_runtime.h>
#include <cuda_bf16.h>
#include <cstdint>

#define K_TAGS 64
#define T_SEQ 128
#define B_SEQ 512
#define D_DIM 512
#define BOS_TAG 63
#define EOS_TAG 62

// Scratch: per-token emission logits WB[token][tag]
__device__ float g_emitWB[(size_t)B_SEQ * T_SEQ * K_TAGS];
// bf16 copy of ThetaB, rebuilt every launch (deterministic)
__device__ __nv_bfloat16 g_tb[K_TAGS * D_DIM];

// ---------------------------------------------------------------------------
// helpers
// ---------------------------------------------------------------------------
__device__ __forceinline__ uint32_t smem_u32(const void* p) {
    return (uint32_t)__cvta_generic_to_shared(p);
}

#define CP_ASYNC16(dst, src) \
    asm volatile("cp.async.cg.shared.global [%0], [%1], 16;\n" ::"r"(dst), "l"(src))
#define CP_COMMIT() asm volatile("cp.async.commit_group;\n")
#define CP_WAIT0() asm volatile("cp.async.wait_group 0;\n")

__device__ __forceinline__ void ldsm4(uint32_t& r0, uint32_t& r1, uint32_t& r2, uint32_t& r3,
                                      uint32_t addr) {
    asm volatile("ldmatrix.sync.aligned.m8n8.x4.shared.b16 {%0,%1,%2,%3}, [%4];"
                 : "=r"(r0), "=r"(r1), "=r"(r2), "=r"(r3) : "r"(addr));
}

__device__ __forceinline__ void mma_bf16(float& c0, float& c1, float& c2, float& c3,
                                         uint32_t a0, uint32_t a1, uint32_t a2, uint32_t a3,
                                         uint32_t b0, uint32_t b1) {
    asm volatile(
        "mma.sync.aligned.m16n8k16.row.col.f32.bf16.bf16.f32 "
        "{%0,%1,%2,%3},{%4,%5,%6,%7},{%8,%9},{%0,%1,%2,%3};"
        : "+f"(c0), "+f"(c1), "+f"(c2), "+f"(c3)
        : "r"(a0), "r"(a1), "r"(a2), "r"(a3), "r"(b0), "r"(b1));
}

// d = { hi = convert(fo), lo = convert(fe) }
__device__ __forceinline__ uint32_t bf2(float fo, float fe) {
    uint32_t d;
    asm("cvt.rn.bf16x2.f32 %0, %1, %2;" : "=r"(d) : "f"(fo), "f"(fe));
    return d;
}

// ---------------------------------------------------------------------------
// Kernel 0: convert ThetaB [64,512] f32 -> bf16 (once per launch)
// ---------------------------------------------------------------------------
__global__ void tb_convert(const float* __restrict__ ThetaB) {
    const int i = blockIdx.x * 256 + threadIdx.x;       // 16384 float2
    const float2 v = ((const float2*)ThetaB)[i];
    ((uint32_t*)g_tb)[i] = bf2(v.y, v.x);
}

// ---------------------------------------------------------------------------
// Kernel 1: gathered emission GEMM, bf16 m16n8k16 + ldmatrix.
// Block: 128 threads (4 warps), 64 tokens x 64 tags, K=512 in 8 chunks of 64.
// smem tiles: 64 rows x 128B (64 bf16), 16B-chunk XOR swizzle (^ row&7).
// B double-buffered via cp.async (bf16 source g_tb); E staged via
// LDG.f32 -> cvt -> STS with next-chunk LDG issued before current compute.
// ---------------------------------------------------------------------------
__global__ __launch_bounds__(128) void emit_kernel(
    const float* __restrict__ E,        // [100000, 512] f32
    const int*   __restrict__ words)    // [B*T]
{
    __shared__ __align__(16) uint8_t sA[2][64 * 128];
    __shared__ __align__(16) uint8_t sB[2][64 * 128];
    __shared__ int sW[64];

    const int tid  = threadIdx.x;
    const int base = blockIdx.x * 64;

    if (tid < 64) sW[tid] = words[base + tid];
    __syncthreads();

    // ---- staging role: thread -> row r, half h (chunks h*4..h*4+3) ----
    const int r = tid >> 1;
    const int h = tid & 1;
    const float* erow = E + (size_t)sW[r] * D_DIM;
    const char*  brow = (const char*)g_tb + (size_t)r * (D_DIM * 2);

    uint32_t stoff[4];     // swizzled byte offset within tile for chunk h*4+i
#pragma unroll
    for (int i = 0; i < 4; i++)
        stoff[i] = r * 128 + (((h * 4 + i) ^ (r & 7)) << 4);

    const uint32_t sA0 = smem_u32(sA[0]), sA1 = smem_u32(sA[1]);
    const uint32_t sB0 = smem_u32(sB[0]), sB1 = smem_u32(sB[1]);

    // ---- compute role ----
    const int lane  = tid & 31;
    const int wbase = (tid >> 5) * 16;                  // warp token offset
    const int g     = lane >> 2;
    const int tg    = lane & 3;
    // A ldmatrix: row + k-half select
    const int a_row = wbase + (lane & 15);
    const int a_sel = lane >> 4;                        // 0: k 0-7, 1: k 8-15
    const uint32_t a_roff = a_row * 128;
    const int a_s7 = a_row & 7;
    // B ldmatrix: covers n-tiles (2j, 2j+1)
    const int b_row_half = (((lane >> 4) & 1) << 3) + (lane & 7);
    const int b_sel = (lane >> 3) & 1;
    const uint32_t b_roff = b_row_half * 128;
    const int b_s7 = b_row_half & 7;

    float acc[8][4];
#pragma unroll
    for (int n = 0; n < 8; n++)
#pragma unroll
        for (int q = 0; q < 4; q++) acc[n][q] = 0.f;

    float4 f[8];

    // ---- prologue: chunk 0 ----
#pragma unroll
    for (int i = 0; i < 4; i++)
        CP_ASYNC16(sB0 + stoff[i], brow + (h * 4 + i) * 16);
    CP_COMMIT();
    {
        const float4* src = (const float4*)(erow + h * 32);
#pragma unroll
        for (int i = 0; i < 8; i++) f[i] = src[i];
#pragma unroll
        for (int i = 0; i < 4; i++) {
            uint4 v;
            v.x = bf2(f[2 * i].y,     f[2 * i].x);
            v.y = bf2(f[2 * i].w,     f[2 * i].z);
            v.z = bf2(f[2 * i + 1].y, f[2 * i + 1].x);
            v.w = bf2(f[2 * i + 1].w, f[2 * i + 1].z);
            *(uint4*)(sA[0] + stoff[i]) = v;
        }
    }
    CP_WAIT0();
    __syncthreads();

    // ---- main loop over 8 chunks of K=64 ----
    for (int c = 0; c < 8; ++c) {
        const uint32_t aBase = (c & 1) ? sA1 : sA0;
        const uint32_t bBase = (c & 1) ? sB1 : sB0;
        const uint32_t aNext = (c & 1) ? sA0 : sA1;
        const uint32_t bNext = (c & 1) ? sB0 : sB1;

        if (c < 7) {
            // prefetch B (cp.async) and E (LDG into regs) for chunk c+1
#pragma unroll
            for (int i = 0; i < 4; i++)
                CP_ASYNC16(bNext + stoff[i], brow + (c + 1) * 128 + (h * 4 + i) * 16);
            CP_COMMIT();
            const float4* src = (const float4*)(erow + (c + 1) * 64 + h * 32);
#pragma unroll
            for (int i = 0; i < 8; i++) f[i] = src[i];
        }

        // compute chunk c: 4 k16-steps
#pragma unroll
        for (int kk = 0; kk < 4; ++kk) {
            uint32_t a0, a1, a2, a3;
            ldsm4(a0, a1, a2, a3,
                  aBase + a_roff + ((uint32_t)((2 * kk + a_sel) ^ a_s7) << 4));
#pragma unroll
            for (int j = 0; j < 4; ++j) {
                uint32_t b0, b1, b2, b3;
                ldsm4(b0, b1, b2, b3,
                      bBase + j * 2048 + b_roff +
                      ((uint32_t)((2 * kk + b_sel) ^ b_s7) << 4));
                mma_bf16(acc[2 * j][0], acc[2 * j][1], acc[2 * j][2], acc[2 * j][3],
                         a0, a1, a2, a3, b0, b1);
                mma_bf16(acc[2 * j + 1][0], acc[2 * j + 1][1], acc[2 * j + 1][2], acc[2 * j + 1][3],
                         a0, a1, a2, a3, b2, b3);
            }
        }

        if (c < 7) {
            // convert + store E chunk c+1 (LDG latency hidden by compute above)
#pragma unroll
            for (int i = 0; i < 4; i++) {
                uint4 v;
                v.x = bf2(f[2 * i].y,     f[2 * i].x);
                v.y = bf2(f[2 * i].w,     f[2 * i].z);
                v.z = bf2(f[2 * i + 1].y, f[2 * i + 1].x);
                v.w = bf2(f[2 * i + 1].w, f[2 * i + 1].z);
                asm volatile("st.shared.v4.b32 [%0], {%1,%2,%3,%4};"
                             :: "r"(aNext + stoff[i]), "r"(v.x), "r"(v.y), "r"(v.z), "r"(v.w));
            }
            CP_WAIT0();
            __syncthreads();
        }
    }

    // ---- epilogue: write WB logits ----
#pragma unroll
    for (int n = 0; n < 8; n++) {
        const int tag  = n * 8 + tg * 2;
        const int row0 = base + wbase + g;
        *(float2*)&g_emitWB[(size_t)row0 * 64 + tag] = make_float2(acc[n][0], acc[n][1]);
        *(float2*)&g_emitWB[(size_t)(row0 + 8) * 64 + tag] = make_float2(acc[n][2], acc[n][3]);
    }
}

// ---------------------------------------------------------------------------
// Kernel 2: per-sequence forward recursion (unsup) + exact tagged log-prob.
// Block = 64 threads = 1 sequence. Thread j owns column j of A = exp(WA).
// Fixed 1/64 per-step scaling (exact in log space) -> no max/shfl/log in loop.
// ---------------------------------------------------------------------------
__global__ __launch_bounds__(64) void forward_kernel(
    const float* __restrict__ WA,     // [64, 64]
    const int*   __restrict__ tags,   // [B*T]
    float*       __restrict__ out)    // [B]
{
    const int b = blockIdx.x;
    const int j = threadIdx.x;

    __shared__ __align__(16) float alpha[2][64];
    __shared__ float red[64];
    __shared__ float s_tagged;

    float Acol[64];
#pragma unroll
    for (int i = 0; i < 64; i++) {
        float wa = WA[i * 64 + j];
        Acol[i] = (j == BOS_TAG) ? 0.f : __expf(wa);
    }

    // ---- tagged path: exact log-domain sum ----
    float loc = 0.f;
    for (int t = j + 1; t <= 126; t += 64) {
        const int tg = tags[b * T_SEQ + t];
        const int pv = (t == 1) ? BOS_TAG : tags[b * T_SEQ + t - 1];
        loc += WA[pv * 64 + tg] + g_emitWB[(size_t)(b * T_SEQ + t) * 64 + tg];
    }
    if (j == 0) loc += WA[tags[b * T_SEQ + 126] * 64 + EOS_TAG];
    red[j] = loc;
    __syncthreads();
#pragma unroll
    for (int s = 32; s > 0; s >>= 1) {
        if (j < s) red[j] += red[j + s];
        __syncthreads();
    }
    if (j == 0) s_tagged = red[0];

    // ---- unsup forward recursion ----
    alpha[0][j] = (j == BOS_TAG) ? 1.f : 0.f;
    __syncthreads();

    const float* wbp = &g_emitWB[(size_t)(b * T_SEQ + 1) * 64 + j];
    float e = (j >= EOS_TAG) ? 0.f : __expf(wbp[0]);

    int p = 0;
    for (int t = 1; t <= 126; ++t) {
        const float wb_next = wbp[(size_t)t * 64];

        float v0 = 0.f, v1 = 0.f, v2 = 0.f, v3 = 0.f;
        float v4 = 0.f, v5 = 0.f, v6 = 0.f, v7 = 0.f;
#pragma unroll
        for (int i = 0; i < 64; i += 8) {
            float4 a4 = *(const float4*)&alpha[p][i];
            float4 b4 = *(const float4*)&alpha[p][i + 4];
            v0 = fmaf(a4.x, Acol[i],     v0);
            v1 = fmaf(a4.y, Acol[i + 1], v1);
            v2 = fmaf(a4.z, Acol[i + 2], v2);
            v3 = fmaf(a4.w, Acol[i + 3], v3);
            v4 = fmaf(b4.x, Acol[i + 4], v4);
            v5 = fmaf(b4.y, Acol[i + 5], v5);
            v6 = fmaf(b4.z, Acol[i + 6], v6);
            v7 = fmaf(b4.w, Acol[i + 7], v7);
        }
        float v = (((v0 + v1) + (v2 + v3)) + ((v4 + v5) + (v6 + v7))) * e * 0.015625f;

        alpha[1 - p][j] = v;
        __syncthreads();

        e = (j >= EOS_TAG) ? 0.f : __expf(wb_next);
        p ^= 1;
    }

    if (j == EOS_TAG) {
        float v = 0.f;
#pragma unroll
        for (int i = 0; i < 64; i++) v = fmaf(alpha[p][i], Acol[i], v);
        const float logZ_unsup = logf(v) + 126.0f * logf(64.0f);
        out[b] = s_tagged - logZ_unsup;
    }
}

// ---------------------------------------------------------------------------
extern "C" void kernel_launch(void* const* d_in, const int* in_sizes, int n_in,
                              void* d_out, int out_size) {
    const float* WA     = (const float*)d_in[0];
    const float* ThetaB = (const float*)d_in[1];
    const float* E      = (const float*)d_in[2];
    const int*   words  = (const int*)d_in[3];
    const int*   tags   = (const int*)d_in[4];
    float* out = (float*)d_out;

    tb_convert<<<64, 256>>>(ThetaB);
    emit_kernel<<<(B_SEQ * T_SEQ) / 64, 128>>>(E, words);
    forward_kernel<<<B_SEQ, 64>>>(WA, tags, out);
}

// round 6
// speedup vs baseline: 2.1538x; 1.0195x over previous
#include <cuda_runtime.h>
#include <cuda_bf16.h>
#include <cstdint>

#define K_TAGS 64
#define T_SEQ 128
#define B_SEQ 512
#define D_DIM 512
#define BOS_TAG 63
#define EOS_TAG 62

typedef unsigned long long ull;

// Scratch: per-token emission logits, bf16
__device__ __nv_bfloat16 g_emitWB[(size_t)B_SEQ * T_SEQ * K_TAGS];
// bf16 copy of ThetaB, rebuilt every launch
__device__ __nv_bfloat16 g_tb[K_TAGS * D_DIM];

// ---------------------------------------------------------------------------
// helpers
// ---------------------------------------------------------------------------
__device__ __forceinline__ uint32_t smem_u32(const void* p) {
    return (uint32_t)__cvta_generic_to_shared(p);
}

#define CP_ASYNC16(dst, src) \
    asm volatile("cp.async.cg.shared.global [%0], [%1], 16;\n" ::"r"(dst), "l"(src))
#define CP_COMMIT() asm volatile("cp.async.commit_group;\n")
#define CP_WAIT(n) asm volatile("cp.async.wait_group %0;\n" ::"n"(n))

__device__ __forceinline__ void ldsm4(uint32_t& r0, uint32_t& r1, uint32_t& r2, uint32_t& r3,
                                      uint32_t addr) {
    asm volatile("ldmatrix.sync.aligned.m8n8.x4.shared.b16 {%0,%1,%2,%3}, [%4];"
                 : "=r"(r0), "=r"(r1), "=r"(r2), "=r"(r3) : "r"(addr));
}

__device__ __forceinline__ void mma_bf16(float& c0, float& c1, float& c2, float& c3,
                                         uint32_t a0, uint32_t a1, uint32_t a2, uint32_t a3,
                                         uint32_t b0, uint32_t b1) {
    asm volatile(
        "mma.sync.aligned.m16n8k16.row.col.f32.bf16.bf16.f32 "
        "{%0,%1,%2,%3},{%4,%5,%6,%7},{%8,%9},{%0,%1,%2,%3};"
        : "+f"(c0), "+f"(c1), "+f"(c2), "+f"(c3)
        : "r"(a0), "r"(a1), "r"(a2), "r"(a3), "r"(b0), "r"(b1));
}

// d = { hi = convert(fo), lo = convert(fe) }
__device__ __forceinline__ uint32_t bf2(float fo, float fe) {
    uint32_t d;
    asm("cvt.rn.bf16x2.f32 %0, %1, %2;" : "=r"(d) : "f"(fo), "f"(fe));
    return d;
}

#define FMA2(d, a, b) asm("fma.rn.f32x2 %0, %1, %2, %0;" : "+l"(d) : "l"(a), "l"(b))
#define ADD2(d, a)    asm("add.rn.f32x2 %0, %1, %0;"     : "+l"(d) : "l"(a))

// ---------------------------------------------------------------------------
// Kernel 0: convert ThetaB [64,512] f32 -> bf16
// ---------------------------------------------------------------------------
__global__ void tb_convert(const float* __restrict__ ThetaB) {
    const int i = blockIdx.x * 256 + threadIdx.x;       // 16384 float2
    const float2 v = ((const float2*)ThetaB)[i];
    ((uint32_t*)g_tb)[i] = bf2(v.y, v.x);
}

// ---------------------------------------------------------------------------
// Kernel 1: gathered emission GEMM, bf16 m16n8k16 + ldmatrix.
// Deep cp.async pipeline: E staged f32 (3 stages, DRAM latency cover ~2-3
// chunk-times), converted to bf16 via own-thread LDS->cvt->STS into
// double-buffered ldmatrix tiles. B bf16 from g_tb, 4 stages.
// Dynamic smem layout (bytes):
//   [0,      49152)  EF : 3 x (64 rows x 256B)   E f32 stages
//   [49152,  81920)  SB : 4 x (64 rows x 128B)   B bf16 stages
//   [81920,  98304)  SA : 2 x (64 rows x 128B)   A bf16 compute tiles
//   [98304,  98560)  sW : 64 ints
// ---------------------------------------------------------------------------
#define EMIT_SMEM 98560

__global__ __launch_bounds__(128) void emit_kernel(
    const float* __restrict__ E,        // [100000, 512] f32
    const int*   __restrict__ words)    // [B*T]
{
    extern __shared__ __align__(16) char dsm[];
    const uint32_t EF = smem_u32(dsm);
    const uint32_t SB = EF + 49152;
    const uint32_t SA = EF + 81920;
    int* sW = (int*)(dsm + 98304);

    const int tid  = threadIdx.x;
    const int base = blockIdx.x * 64;

    if (tid < 64) sW[tid] = words[base + tid];
    __syncthreads();

    // staging role: row r, half h
    const int r = tid >> 1;
    const int h = tid & 1;
    const int s7 = r & 7;
    const char* erow = (const char*)(E + (size_t)sW[r] * D_DIM);
    const char* brow = (const char*)g_tb + (size_t)r * (D_DIM * 2);

    // compute role
    const int lane  = tid & 31;
    const int wbase = (tid >> 5) * 16;
    const int g     = lane >> 2;
    const int tg    = lane & 3;
    const int a_row = wbase + (lane & 15);
    const int a_sel = lane >> 4;
    const uint32_t a_roff = a_row * 128;
    const int a_s7 = a_row & 7;
    const int b_row_half = (((lane >> 4) & 1) << 3) + (lane & 7);
    const int b_sel = (lane >> 3) & 1;
    const uint32_t b_roff = b_row_half * 128;
    const int b_s7 = b_row_half & 7;

    float acc[8][4];
#pragma unroll
    for (int n = 0; n < 8; n++)
#pragma unroll
        for (int q = 0; q < 4; q++) acc[n][q] = 0.f;

    // ---- stage-issue: own-thread units ----
    // E f32 units u = h*8 .. h*8+7 (16B each), swizzled u^(r&7) within 256B row
    // B bf16 units j = h*4 .. h*4+3 (16B each), swizzled j^(r&7) within 128B row
#define EMIT_STAGE(chunk)                                                         \
    do {                                                                          \
        const uint32_t efs = EF + ((chunk) % 3) * 16384 + r * 256;                \
        const uint32_t sbs = SB + ((chunk) % 4) * 8192 + r * 128;                 \
        _Pragma("unroll")                                                         \
        for (int i = 0; i < 8; i++) {                                             \
            const int u = h * 8 + i;                                              \
            CP_ASYNC16(efs + ((u ^ s7) << 4), erow + (chunk) * 256 + u * 16);     \
        }                                                                         \
        _Pragma("unroll")                                                         \
        for (int i = 0; i < 4; i++) {                                             \
            const int j = h * 4 + i;                                              \
            CP_ASYNC16(sbs + ((j ^ s7) << 4), brow + (chunk) * 128 + j * 16);     \
        }                                                                         \
        CP_COMMIT();                                                              \
    } while (0)

    // prologue: chunks 0..2
    EMIT_STAGE(0);
    EMIT_STAGE(1);
    EMIT_STAGE(2);

#pragma unroll
    for (int c = 0; c < 8; ++c) {
        // wait for chunk c's group
        if (c <= 5)      CP_WAIT(2);
        else if (c == 6) CP_WAIT(1);
        else             CP_WAIT(0);

        // convert own-thread E f32 -> bf16 into SA[c&1]
        {
            const uint32_t efs = EF + (c % 3) * 16384 + r * 256;
            const uint32_t sas = SA + (c & 1) * 8192 + r * 128;
#pragma unroll
            for (int i = 0; i < 4; i++) {
                const int j = h * 4 + i;
                float f0, f1, f2, f3, f4, f5, f6, f7;
                asm volatile("ld.shared.v4.f32 {%0,%1,%2,%3}, [%4];"
                             : "=f"(f0), "=f"(f1), "=f"(f2), "=f"(f3)
                             : "r"(efs + (((2 * j) ^ s7) << 4)));
                asm volatile("ld.shared.v4.f32 {%0,%1,%2,%3}, [%4];"
                             : "=f"(f4), "=f"(f5), "=f"(f6), "=f"(f7)
                             : "r"(efs + (((2 * j + 1) ^ s7) << 4)));
                uint32_t v0 = bf2(f1, f0);
                uint32_t v1 = bf2(f3, f2);
                uint32_t v2 = bf2(f5, f4);
                uint32_t v3 = bf2(f7, f6);
                asm volatile("st.shared.v4.b32 [%0], {%1,%2,%3,%4};"
                             :: "r"(sas + ((j ^ s7) << 4)),
                                "r"(v0), "r"(v1), "r"(v2), "r"(v3));
            }
        }

        __syncthreads();

        // commit next stage AFTER the barrier: slot (c+3)%4 / (c+3)%3 is only
        // re-written once every warp has passed this barrier.
        if (c + 3 < 8) EMIT_STAGE(c + 3);

        // compute chunk c
        const uint32_t aBase = SA + (c & 1) * 8192;
        const uint32_t bBase = SB + (c % 4) * 8192;
#pragma unroll
        for (int kk = 0; kk < 4; ++kk) {
            uint32_t a0, a1, a2, a3;
            ldsm4(a0, a1, a2, a3,
                  aBase + a_roff + ((uint32_t)((2 * kk + a_sel) ^ a_s7) << 4));
#pragma unroll
            for (int j = 0; j < 4; ++j) {
                uint32_t b0, b1, b2, b3;
                ldsm4(b0, b1, b2, b3,
                      bBase + j * 2048 + b_roff +
                      ((uint32_t)((2 * kk + b_sel) ^ b_s7) << 4));
                mma_bf16(acc[2 * j][0], acc[2 * j][1], acc[2 * j][2], acc[2 * j][3],
                         a0, a1, a2, a3, b0, b1);
                mma_bf16(acc[2 * j + 1][0], acc[2 * j + 1][1], acc[2 * j + 1][2], acc[2 * j + 1][3],
                         a0, a1, a2, a3, b2, b3);
            }
        }
    }

    // ---- epilogue: write WB logits as bf16 ----
#pragma unroll
    for (int n = 0; n < 8; n++) {
        const int tag  = n * 8 + tg * 2;
        const int row0 = base + wbase + g;
        *(uint32_t*)&g_emitWB[(size_t)row0 * 64 + tag]       = bf2(acc[n][1], acc[n][0]);
        *(uint32_t*)&g_emitWB[(size_t)(row0 + 8) * 64 + tag] = bf2(acc[n][3], acc[n][2]);
    }
}

// ---------------------------------------------------------------------------
// Kernel 2: per-sequence forward recursion + exact tagged log-prob.
// Block = 64 threads = 1 sequence. Emissions bulk-loaded to smem via cp.async
// (overlapped with Acol exp). Matvec in packed f32x2 FMA. Fixed 1/64 scaling.
// ---------------------------------------------------------------------------
__global__ __launch_bounds__(64) void forward_kernel(
    const float* __restrict__ WA,     // [64, 64]
    const int*   __restrict__ tags,   // [B*T]
    float*       __restrict__ out)    // [B]
{
    const int b = blockIdx.x;
    const int j = threadIdx.x;

    __shared__ __align__(16) __nv_bfloat16 sEmit[T_SEQ * K_TAGS];   // 16KB
    __shared__ __align__(16) float alpha[2][64];
    __shared__ float red[64];
    __shared__ float s_tagged;

    // bulk-load this sequence's emissions (16KB) into smem
    {
        const char* src = (const char*)g_emitWB + (size_t)b * (T_SEQ * K_TAGS * 2);
        const uint32_t dst = smem_u32(sEmit) + j * 256;
#pragma unroll
        for (int i = 0; i < 16; i++)
            CP_ASYNC16(dst + i * 16, src + j * 256 + i * 16);
        CP_COMMIT();
    }

    // A column j as 32 packed f32x2 pairs: A[2i..2i+1][j]
    ull A2[32];
#pragma unroll
    for (int i = 0; i < 32; i++) {
        float lo = (j == BOS_TAG) ? 0.f : __expf(WA[(2 * i) * 64 + j]);
        float hi = (j == BOS_TAG) ? 0.f : __expf(WA[(2 * i + 1) * 64 + j]);
        A2[i] = ((ull)__float_as_uint(hi) << 32) | __float_as_uint(lo);
    }

    CP_WAIT(0);
    __syncthreads();

    // ---- tagged path: exact log-domain sum (reads smem emissions) ----
    float loc = 0.f;
    for (int t = j + 1; t <= 126; t += 64) {
        const int tg = tags[b * T_SEQ + t];
        const int pv = (t == 1) ? BOS_TAG : tags[b * T_SEQ + t - 1];
        loc += WA[pv * 64 + tg] + __bfloat162float(sEmit[t * 64 + tg]);
    }
    if (j == 0) loc += WA[tags[b * T_SEQ + 126] * 64 + EOS_TAG];
    red[j] = loc;
    __syncthreads();
#pragma unroll
    for (int s = 32; s > 0; s >>= 1) {
        if (j < s) red[j] += red[j + s];
        __syncthreads();
    }
    if (j == 0) s_tagged = red[0];

    // ---- unsup forward recursion ----
    alpha[0][j] = (j == BOS_TAG) ? 1.f : 0.f;
    __syncthreads();

    float e = (j >= EOS_TAG) ? 0.f : __expf(__bfloat162float(sEmit[64 + j]));

    int p = 0;
    for (int t = 1; t <= 126; ++t) {
        const __nv_bfloat16 wb_next = sEmit[(t + 1) * 64 + j];   // t=126 -> row 127, unused

        ull acc[8] = {0, 0, 0, 0, 0, 0, 0, 0};
#pragma unroll
        for (int i = 0; i < 16; i++) {
            const ulonglong2 q = *(const ulonglong2*)&alpha[p][i * 4];
            FMA2(acc[(2 * i) & 7],     q.x, A2[2 * i]);
            FMA2(acc[(2 * i + 1) & 7], q.y, A2[2 * i + 1]);
        }
        ADD2(acc[0], acc[4]); ADD2(acc[1], acc[5]);
        ADD2(acc[2], acc[6]); ADD2(acc[3], acc[7]);
        ADD2(acc[0], acc[2]); ADD2(acc[1], acc[3]);
        ADD2(acc[0], acc[1]);
        const float vlo = __uint_as_float((unsigned)(acc[0] & 0xffffffffull));
        const float vhi = __uint_as_float((unsigned)(acc[0] >> 32));
        const float v = (vlo + vhi) * e * 0.015625f;

        alpha[1 - p][j] = v;
        __syncthreads();

        e = (j >= EOS_TAG) ? 0.f : __expf(__bfloat162float(wb_next));
        p ^= 1;
    }

    // ---- termination: thread 62 holds A[:, EOS] in A2 ----
    if (j == EOS_TAG) {
        float s = 0.f;
#pragma unroll
        for (int i = 0; i < 32; i++) {
            const float alo = __uint_as_float((unsigned)(A2[i] & 0xffffffffull));
            const float ahi = __uint_as_float((unsigned)(A2[i] >> 32));
            s = fmaf(alpha[p][2 * i], alo, s);
            s = fmaf(alpha[p][2 * i + 1], ahi, s);
        }
        const float logZ_unsup = logf(s) + 126.0f * logf(64.0f);
        out[b] = s_tagged - logZ_unsup;
    }
}

// ---------------------------------------------------------------------------
extern "C" void kernel_launch(void* const* d_in, const int* in_sizes, int n_in,
                              void* d_out, int out_size) {
    const float* WA     = (const float*)d_in[0];
    const float* ThetaB = (const float*)d_in[1];
    const float* E      = (const float*)d_in[2];
    const int*   words  = (const int*)d_in[3];
    const int*   tags   = (const int*)d_in[4];
    float* out = (float*)d_out;

    cudaFuncSetAttribute(emit_kernel, cudaFuncAttributeMaxDynamicSharedMemorySize,
                         EMIT_SMEM);

    tb_convert<<<64, 256>>>(ThetaB);
    emit_kernel<<<(B_SEQ * T_SEQ) / 64, 128, EMIT_SMEM>>>(E, words);
    forward_kernel<<<B_SEQ, 64>>>(WA, tags, out);
}